// round 1
// baseline (speedup 1.0000x reference)
#include <cuda_runtime.h>
#include <math.h>

#define BATCH   2
#define SEQ     2048
#define DMODEL  1024
#define NHEADS  16
#define HDIM    64
#define MROWS   (BATCH*SEQ)        // 4096
#define EDIM    (3*DMODEL)         // 3072

// Scratch (device globals; no runtime allocation allowed)
__device__ float g_h[MROWS*DMODEL];        // 16 MB  (rmsnorm output)
__device__ float g_qkv[MROWS*EDIM];        // 48 MB  (qkv, rope applied in place)
__device__ float g_attn[MROWS*DMODEL];     // 16 MB  (attention output pre-projection)

// ---------------------------------------------------------------------------
// K1: RMSNorm. One block per row of 1024, 256 threads.
// ---------------------------------------------------------------------------
__global__ void rmsnorm_kernel(const float* __restrict__ x, const float* __restrict__ w) {
    int row = blockIdx.x;
    int tid = threadIdx.x;
    const float* xr = x + (size_t)row * DMODEL;
    float v[4];
    float ss = 0.f;
#pragma unroll
    for (int i = 0; i < 4; i++) { v[i] = xr[tid + i*256]; ss += v[i]*v[i]; }
    __shared__ float red[256];
    red[tid] = ss;
    __syncthreads();
#pragma unroll
    for (int off = 128; off > 0; off >>= 1) {
        if (tid < off) red[tid] += red[tid + off];
        __syncthreads();
    }
    float inv = rsqrtf(red[0] * (1.0f / DMODEL) + 1e-6f);
    float* hr = g_h + (size_t)row * DMODEL;
#pragma unroll
    for (int i = 0; i < 4; i++) hr[tid + i*256] = v[i] * inv * w[tid + i*256];
}

// ---------------------------------------------------------------------------
// K2/K5: NT GEMM  C[M,N] = A[M,K] * B[N,K]^T  (+ optional residual).
// 64x64 tile, BK=16, 256 threads (16x16), 4x4 per thread.
// ---------------------------------------------------------------------------
template<bool RES>
__global__ void gemm_nt_kernel(const float* __restrict__ A, const float* __restrict__ Bw,
                               const float* __restrict__ Rsd, float* __restrict__ C,
                               int M, int N, int K) {
    __shared__ float As[64][17];
    __shared__ float Bs[64][17];
    int tid = threadIdx.x;
    int tx = tid & 15, ty = tid >> 4;
    int m0 = blockIdx.y * 64, n0 = blockIdx.x * 64;
    int lr = tid >> 2;          // 0..63
    int lk = (tid & 3) * 4;     // 0,4,8,12
    float acc[4][4] = {};
    for (int k0 = 0; k0 < K; k0 += 16) {
        float4 av = *(const float4*)(A  + (size_t)(m0 + lr) * K + k0 + lk);
        float4 bv = *(const float4*)(Bw + (size_t)(n0 + lr) * K + k0 + lk);
        As[lr][lk+0] = av.x; As[lr][lk+1] = av.y; As[lr][lk+2] = av.z; As[lr][lk+3] = av.w;
        Bs[lr][lk+0] = bv.x; Bs[lr][lk+1] = bv.y; Bs[lr][lk+2] = bv.z; Bs[lr][lk+3] = bv.w;
        __syncthreads();
#pragma unroll
        for (int k = 0; k < 16; k++) {
            float a[4], b[4];
#pragma unroll
            for (int r = 0; r < 4; r++) a[r] = As[ty*4 + r][k];
#pragma unroll
            for (int c = 0; c < 4; c++) b[c] = Bs[tx*4 + c][k];
#pragma unroll
            for (int r = 0; r < 4; r++)
#pragma unroll
                for (int c = 0; c < 4; c++) acc[r][c] += a[r] * b[c];
        }
        __syncthreads();
    }
#pragma unroll
    for (int r = 0; r < 4; r++) {
        int m = m0 + ty*4 + r;
#pragma unroll
        for (int c = 0; c < 4; c++) {
            int n = n0 + tx*4 + c;
            float val = acc[r][c];
            if (RES) val += Rsd[(size_t)m * N + n];
            C[(size_t)m * N + n] = val;
        }
    }
}

// ---------------------------------------------------------------------------
// K3: RoPE applied in place to q and k sections of g_qkv.
// One thread per (m, section, head, d<32) rotation pair.
// ---------------------------------------------------------------------------
__global__ void rope_kernel() {
    int idx = blockIdx.x * 256 + threadIdx.x;   // < MROWS*2*NHEADS*32 = 4194304
    int d = idx & 31;
    int h = (idx >> 5) & 15;
    int s = (idx >> 9) & 1;
    int m = idx >> 10;
    if (m >= MROWS) return;
    int t = m & (SEQ - 1);
    float inv_freq = powf(10000.0f, -(float)d * (1.0f / 32.0f));
    float ang = (float)t * inv_freq;
    float sn, cs;
    sincosf(ang, &sn, &cs);
    float* p = g_qkv + (size_t)m * EDIM + s * DMODEL + h * HDIM;
    float x1 = p[d], x2 = p[d + 32];
    p[d]      = x1 * cs - x2 * sn;
    p[d + 32] = x2 * cs + x1 * sn;
}

// ---------------------------------------------------------------------------
// K4: causal flash attention, fp32. grid = (SEQ/64, NHEADS, BATCH),
// 256 threads (16x16), 64-query x 64-headdim tile per block, 64-key steps.
// Dynamic smem: Q,K,V,P each [64][65] floats = 66560 bytes.
// ---------------------------------------------------------------------------
__global__ void attn_kernel() {
    extern __shared__ float sm[];
    float (*Qs)[65] = (float(*)[65])(sm);
    float (*Ks)[65] = (float(*)[65])(sm + 64*65);
    float (*Vs)[65] = (float(*)[65])(sm + 2*64*65);
    float (*Ps)[65] = (float(*)[65])(sm + 3*64*65);

    int qt = blockIdx.x, h = blockIdx.y, b = blockIdx.z;
    int tid = threadIdx.x;
    int tx = tid & 15, ty = tid >> 4;
    int q0 = qt * 64;

    int rbase = tid >> 4;          // 0..15
    int dq = (tid & 15) * 4;       // 0..60

    // Load Q tile, pre-scaled by 1/sqrt(64) = 0.125
#pragma unroll
    for (int p = 0; p < 4; p++) {
        int r = p * 16 + rbase;
        float4 v = *(const float4*)(g_qkv + (size_t)(b*SEQ + q0 + r) * EDIM + h*HDIM + dq);
        Qs[r][dq+0] = v.x * 0.125f; Qs[r][dq+1] = v.y * 0.125f;
        Qs[r][dq+2] = v.z * 0.125f; Qs[r][dq+3] = v.w * 0.125f;
    }

    float mr[4], lrow[4], o[4][4];
#pragma unroll
    for (int r = 0; r < 4; r++) {
        mr[r] = -1e30f; lrow[r] = 0.f;
#pragma unroll
        for (int c = 0; c < 4; c++) o[r][c] = 0.f;
    }

    for (int kt = 0; kt <= qt; kt++) {
        __syncthreads();   // guards Q tile on first iter; P/V reads on later iters
        // Load K, V tiles
#pragma unroll
        for (int p = 0; p < 4; p++) {
            int r = p * 16 + rbase;
            size_t base = (size_t)(b*SEQ + kt*64 + r) * EDIM + h*HDIM + dq;
            float4 kv = *(const float4*)(g_qkv + base + DMODEL);
            float4 vv = *(const float4*)(g_qkv + base + 2*DMODEL);
            Ks[r][dq+0] = kv.x; Ks[r][dq+1] = kv.y; Ks[r][dq+2] = kv.z; Ks[r][dq+3] = kv.w;
            Vs[r][dq+0] = vv.x; Vs[r][dq+1] = vv.y; Vs[r][dq+2] = vv.z; Vs[r][dq+3] = vv.w;
        }
        __syncthreads();

        // S = Q K^T  (each thread: rows ty*4.., cols tx*4..)
        float sacc[4][4] = {};
#pragma unroll 8
        for (int d = 0; d < 64; d++) {
            float a[4], bb[4];
#pragma unroll
            for (int r = 0; r < 4; r++) a[r] = Qs[ty*4 + r][d];
#pragma unroll
            for (int c = 0; c < 4; c++) bb[c] = Ks[tx*4 + c][d];
#pragma unroll
            for (int r = 0; r < 4; r++)
#pragma unroll
                for (int c = 0; c < 4; c++) sacc[r][c] += a[r] * bb[c];
        }

        if (kt == qt) {   // diagonal tile causal mask: query i attends keys j<=i
#pragma unroll
            for (int r = 0; r < 4; r++)
#pragma unroll
                for (int c = 0; c < 4; c++)
                    if (ty*4 + r < tx*4 + c) sacc[r][c] = -1e30f;
        }

        // Online softmax per row (row owned by a 16-lane half-warp)
#pragma unroll
        for (int r = 0; r < 4; r++) {
            float rm = fmaxf(fmaxf(sacc[r][0], sacc[r][1]), fmaxf(sacc[r][2], sacc[r][3]));
#pragma unroll
            for (int off = 8; off > 0; off >>= 1)
                rm = fmaxf(rm, __shfl_xor_sync(0xffffffffu, rm, off, 16));
            float mnew = fmaxf(mr[r], rm);
            float pr[4]; float rs = 0.f;
#pragma unroll
            for (int c = 0; c < 4; c++) { pr[c] = __expf(sacc[r][c] - mnew); rs += pr[c]; }
#pragma unroll
            for (int off = 8; off > 0; off >>= 1)
                rs += __shfl_xor_sync(0xffffffffu, rs, off, 16);
            float alpha = __expf(mr[r] - mnew);
            lrow[r] = lrow[r] * alpha + rs;
            mr[r] = mnew;
#pragma unroll
            for (int c = 0; c < 4; c++) o[r][c] *= alpha;
#pragma unroll
            for (int c = 0; c < 4; c++) Ps[ty*4 + r][tx*4 + c] = pr[c];
        }
        __syncthreads();

        // O += P * V   (thread: rows ty*4.., headdim cols tx*4..)
#pragma unroll 8
        for (int j = 0; j < 64; j++) {
            float a[4], bb[4];
#pragma unroll
            for (int r = 0; r < 4; r++) a[r] = Ps[ty*4 + r][j];
#pragma unroll
            for (int c = 0; c < 4; c++) bb[c] = Vs[j][tx*4 + c];
#pragma unroll
            for (int r = 0; r < 4; r++)
#pragma unroll
                for (int c = 0; c < 4; c++) o[r][c] += a[r] * bb[c];
        }
    }

    // Epilogue: normalize and write
#pragma unroll
    for (int r = 0; r < 4; r++) {
        float invl = 1.0f / lrow[r];
        int row = b*SEQ + q0 + ty*4 + r;
#pragma unroll
        for (int c = 0; c < 4; c++)
            g_attn[(size_t)row * DMODEL + h*HDIM + tx*4 + c] = o[r][c] * invl;
    }
}

// ---------------------------------------------------------------------------
extern "C" void kernel_launch(void* const* d_in, const int* in_sizes, int n_in,
                              void* d_out, int out_size) {
    const float* x      = (const float*)d_in[0];
    const float* norm_w = (const float*)d_in[1];
    const float* w_qkv  = (const float*)d_in[2];
    const float* w_out  = (const float*)d_in[3];
    float* out = (float*)d_out;

    float *p_h, *p_qkv, *p_attn;
    cudaGetSymbolAddress((void**)&p_h,    g_h);
    cudaGetSymbolAddress((void**)&p_qkv,  g_qkv);
    cudaGetSymbolAddress((void**)&p_attn, g_attn);

    // 1. RMSNorm
    rmsnorm_kernel<<<MROWS, 256>>>(x, norm_w);

    // 2. QKV projection: [4096,3072] = h[4096,1024] @ w_qkv[3072,1024]^T
    gemm_nt_kernel<false><<<dim3(EDIM/64, MROWS/64), 256>>>(
        p_h, w_qkv, nullptr, p_qkv, MROWS, EDIM, DMODEL);

    // 3. RoPE (in place on q,k sections)
    rope_kernel<<<(MROWS * 2 * NHEADS * 32) / 256, 256>>>();

    // 4. Causal flash attention
    int smem = 4 * 64 * 65 * (int)sizeof(float);   // 66560
    cudaFuncSetAttribute(attn_kernel, cudaFuncAttributeMaxDynamicSharedMemorySize, smem);
    attn_kernel<<<dim3(SEQ/64, NHEADS, BATCH), 256, smem>>>();

    // 5. Output projection + residual: out = x + attn @ w_out^T
    gemm_nt_kernel<true><<<dim3(DMODEL/64, MROWS/64), 256>>>(
        p_attn, w_out, x, out, MROWS, DMODEL, DMODEL);
}

// round 3
// speedup vs baseline: 1.4675x; 1.4675x over previous
#include <cuda_runtime.h>
#include <cuda_bf16.h>
#include <math.h>
#include <stdint.h>

#define BATCH   2
#define SEQ     2048
#define DMODEL  1024
#define NHEADS  16
#define HDIM    64
#define MROWS   (BATCH*SEQ)        // 4096
#define EDIM    (3*DMODEL)         // 3072
#define K3      (3*DMODEL)         // expanded split-K = 3072
#define NK      (K3/32)            // 96 k-chunks of 32

// Scratch (device globals; no runtime allocation allowed)
__device__ __align__(128) __nv_bfloat16 g_abf[MROWS*K3];     // A' (hi,lo,hi)
__device__ __align__(128) __nv_bfloat16 g_bbf[EDIM*K3];      // B' for w_qkv (hi,hi,lo)
__device__ __align__(128) __nv_bfloat16 g_bbf2[DMODEL*K3];   // B' for w_out
__device__ float g_qkv[MROWS*EDIM];
__device__ float g_attn[MROWS*DMODEL];

// ===========================================================================
// helpers
// ===========================================================================
__device__ __forceinline__ uint32_t smem_u32(const void* p) {
    uint32_t a;
    asm("{ .reg .u64 t; cvta.to.shared.u64 t, %1; cvt.u32.u64 %0, t; }" : "=r"(a) : "l"(p));
    return a;
}
__device__ __forceinline__ void cp16(uint32_t smem, const void* g) {
    asm volatile("cp.async.cg.shared.global [%0], [%1], 16;" :: "r"(smem), "l"(g) : "memory");
}
__device__ __forceinline__ void cp_commit() {
    asm volatile("cp.async.commit_group;" ::: "memory");
}
template<int N> __device__ __forceinline__ void cp_wait() {
    asm volatile("cp.async.wait_group %0;" :: "n"(N) : "memory");
}
__device__ __forceinline__ void ldsm4(uint32_t& r0, uint32_t& r1, uint32_t& r2, uint32_t& r3,
                                      uint32_t addr) {
    asm volatile("ldmatrix.sync.aligned.m8n8.x4.shared.b16 {%0,%1,%2,%3}, [%4];"
                 : "=r"(r0), "=r"(r1), "=r"(r2), "=r"(r3) : "r"(addr));
}
__device__ __forceinline__ void mma16816(float* d, const uint32_t* a, const uint32_t* b) {
    asm volatile("mma.sync.aligned.m16n8k16.row.col.f32.bf16.bf16.f32 "
                 "{%0,%1,%2,%3}, {%4,%5,%6,%7}, {%8,%9}, {%0,%1,%2,%3};"
                 : "+f"(d[0]), "+f"(d[1]), "+f"(d[2]), "+f"(d[3])
                 : "r"(a[0]), "r"(a[1]), "r"(a[2]), "r"(a[3]), "r"(b[0]), "r"(b[1]));
}

// ===========================================================================
// K1: RMSNorm -> bf16-split A' (hi, lo, hi). One block per row, 256 threads.
// ===========================================================================
__global__ void rmsnorm_kernel(const float* __restrict__ x, const float* __restrict__ w) {
    int row = blockIdx.x;
    int tid = threadIdx.x;
    const float* xr = x + (size_t)row * DMODEL;
    float v[4];
    float ss = 0.f;
#pragma unroll
    for (int i = 0; i < 4; i++) { v[i] = xr[tid + i*256]; ss += v[i]*v[i]; }
    __shared__ float red[256];
    red[tid] = ss;
    __syncthreads();
#pragma unroll
    for (int off = 128; off > 0; off >>= 1) {
        if (tid < off) red[tid] += red[tid + off];
        __syncthreads();
    }
    float inv = rsqrtf(red[0] * (1.0f / DMODEL) + 1e-6f);
    __nv_bfloat16* d = g_abf + (size_t)row * K3;
#pragma unroll
    for (int i = 0; i < 4; i++) {
        int col = tid + i*256;
        float y = v[i] * inv * w[col];
        __nv_bfloat16 hi = __float2bfloat16(y);
        __nv_bfloat16 lo = __float2bfloat16(y - __bfloat162float(hi));
        d[col] = hi; d[DMODEL + col] = lo; d[2*DMODEL + col] = hi;
    }
}

// ===========================================================================
// Conversion kernels: fp32 [rows,1024] -> bf16-split [rows,3072]
// ===========================================================================
__global__ void convert_w_kernel(const float* __restrict__ src, __nv_bfloat16* __restrict__ dst,
                                 int total) {   // weight layout (hi, hi, lo)
    int idx = blockIdx.x * 256 + threadIdx.x;
    if (idx >= total) return;
    int n = idx >> 10, k = idx & 1023;
    float x = src[idx];
    __nv_bfloat16 hi = __float2bfloat16(x);
    __nv_bfloat16 lo = __float2bfloat16(x - __bfloat162float(hi));
    __nv_bfloat16* d = dst + (size_t)n * K3;
    d[k] = hi; d[DMODEL + k] = hi; d[2*DMODEL + k] = lo;
}
__global__ void convert_a_kernel(const float* __restrict__ src, __nv_bfloat16* __restrict__ dst,
                                 int total) {   // activation layout (hi, lo, hi)
    int idx = blockIdx.x * 256 + threadIdx.x;
    if (idx >= total) return;
    int n = idx >> 10, k = idx & 1023;
    float x = src[idx];
    __nv_bfloat16 hi = __float2bfloat16(x);
    __nv_bfloat16 lo = __float2bfloat16(x - __bfloat162float(hi));
    __nv_bfloat16* d = dst + (size_t)n * K3;
    d[k] = hi; d[DMODEL + k] = lo; d[2*DMODEL + k] = hi;
}

// ===========================================================================
// HMMA GEMM: C[M,N] = A'[M,3072] @ B'[N,3072]^T (+ residual)
// 128x128x32 CTA tile, 256 thr (8 warps, 2x4), warp tile 64x32,
// mma.sync.m16n8k16 bf16, cp.async double buffer, padded smem (stride 40 halfs).
// ===========================================================================
template<bool RES>
__global__ __launch_bounds__(256) void gemm_mma_kernel(
    const __nv_bfloat16* __restrict__ A, const __nv_bfloat16* __restrict__ Bw,
    const float* __restrict__ Rsd, float* __restrict__ C, int N)
{
    __shared__ __align__(128) __nv_bfloat16 sA[2][128*40];
    __shared__ __align__(128) __nv_bfloat16 sB[2][128*40];

    int tid = threadIdx.x, lid = tid & 31, wid = tid >> 5;
    int wm = (wid & 1) * 64;        // warp m offset in tile
    int wn = (wid >> 1) * 32;       // warp n offset in tile
    int m0 = blockIdx.y * 128, n0 = blockIdx.x * 128;

    // global load mapping: each thread owns 32 contiguous bytes of one row
    int ldrow = tid >> 1;
    int ldcol = (tid & 1) * 32;     // byte offset within the 64B (32 bf16) chunk
    const char* gA = (const char*)(A  + (size_t)(m0 + ldrow) * K3) + ldcol;
    const char* gB = (const char*)(Bw + (size_t)(n0 + ldrow) * K3) + ldcol;

    auto prefetch = [&](int c) {
        int s = c & 1;
        uint32_t da = smem_u32(&sA[s][ldrow * 40]) + (uint32_t)ldcol;
        uint32_t db = smem_u32(&sB[s][ldrow * 40]) + (uint32_t)ldcol;
        const char* a = gA + (size_t)c * 64;
        const char* b = gB + (size_t)c * 64;
        cp16(da, a);      cp16(da + 16, a + 16);
        cp16(db, b);      cp16(db + 16, b + 16);
        cp_commit();
    };

    float acc[4][4][4] = {};

    prefetch(0); prefetch(1);

    // ldmatrix lane-address components
    int g  = lid >> 3, r8 = lid & 7;
    int a_m = wm + (g & 1) * 8 + r8;   // + mt*16
    int a_k = (g >> 1) * 8;            // + ks*16
    int b_n = wn + (g >> 1) * 8 + r8;  // + nt*16
    int b_k = (g & 1) * 8;             // + ks*16

    for (int kt = 0; kt < NK; kt++) {
        int s = kt & 1;
        if (kt + 1 < NK) cp_wait<1>(); else cp_wait<0>();
        __syncthreads();

        uint32_t baseA = smem_u32(&sA[s][0]);
        uint32_t baseB = smem_u32(&sB[s][0]);
#pragma unroll
        for (int ks = 0; ks < 2; ks++) {
            uint32_t a[4][4], b[4][2];
#pragma unroll
            for (int mt = 0; mt < 4; mt++) {
                uint32_t addr = baseA + (uint32_t)(a_m + mt*16) * 80u
                                      + (uint32_t)(a_k + ks*16) * 2u;
                ldsm4(a[mt][0], a[mt][1], a[mt][2], a[mt][3], addr);
            }
#pragma unroll
            for (int nt = 0; nt < 2; nt++) {
                uint32_t r0, r1, r2, r3;
                uint32_t addr = baseB + (uint32_t)(b_n + nt*16) * 80u
                                      + (uint32_t)(b_k + ks*16) * 2u;
                ldsm4(r0, r1, r2, r3, addr);
                b[nt*2][0] = r0;   b[nt*2][1] = r1;
                b[nt*2+1][0] = r2; b[nt*2+1][1] = r3;
            }
#pragma unroll
            for (int mt = 0; mt < 4; mt++)
#pragma unroll
                for (int nn = 0; nn < 4; nn++)
                    mma16816(acc[mt][nn], a[mt], b[nn]);
        }
        __syncthreads();
        if (kt + 2 < NK) prefetch(kt + 2);
    }

    // epilogue: c0,c1 at (row, col..col+1); c2,c3 at (row+8, ..)
    int row = lid >> 2, col = (lid & 3) * 2;
#pragma unroll
    for (int mt = 0; mt < 4; mt++) {
#pragma unroll
        for (int nn = 0; nn < 4; nn++) {
            int m = m0 + wm + mt*16 + row;
            int n = n0 + wn + nn*8 + col;
            float2 v0 = make_float2(acc[mt][nn][0], acc[mt][nn][1]);
            float2 v1 = make_float2(acc[mt][nn][2], acc[mt][nn][3]);
            if (RES) {
                float2 q0 = *(const float2*)(Rsd + (size_t)m * N + n);
                float2 q1 = *(const float2*)(Rsd + (size_t)(m+8) * N + n);
                v0.x += q0.x; v0.y += q0.y;
                v1.x += q1.x; v1.y += q1.y;
            }
            *(float2*)(C + (size_t)m * N + n)     = v0;
            *(float2*)(C + (size_t)(m+8) * N + n) = v1;
        }
    }
}

// ===========================================================================
// K3: RoPE applied in place to q and k sections of g_qkv.
// ===========================================================================
__global__ void rope_kernel() {
    int idx = blockIdx.x * 256 + threadIdx.x;
    int d = idx & 31;
    int h = (idx >> 5) & 15;
    int s = (idx >> 9) & 1;
    int m = idx >> 10;
    if (m >= MROWS) return;
    int t = m & (SEQ - 1);
    float inv_freq = powf(10000.0f, -(float)d * (1.0f / 32.0f));
    float ang = (float)t * inv_freq;
    float sn, cs;
    sincosf(ang, &sn, &cs);
    float* p = g_qkv + (size_t)m * EDIM + s * DMODEL + h * HDIM;
    float x1 = p[d], x2 = p[d + 32];
    p[d]      = x1 * cs - x2 * sn;
    p[d + 32] = x2 * cs + x1 * sn;
}

// ===========================================================================
// K4: causal flash attention, fp32 (unchanged, known-good).
// ===========================================================================
__global__ void attn_kernel() {
    extern __shared__ float sm[];
    float (*Qs)[65] = (float(*)[65])(sm);
    float (*Ks)[65] = (float(*)[65])(sm + 64*65);
    float (*Vs)[65] = (float(*)[65])(sm + 2*64*65);
    float (*Ps)[65] = (float(*)[65])(sm + 3*64*65);

    int qt = blockIdx.x, h = blockIdx.y, b = blockIdx.z;
    int tid = threadIdx.x;
    int tx = tid & 15, ty = tid >> 4;
    int q0 = qt * 64;

    int rbase = tid >> 4;
    int dq = (tid & 15) * 4;

#pragma unroll
    for (int p = 0; p < 4; p++) {
        int r = p * 16 + rbase;
        float4 v = *(const float4*)(g_qkv + (size_t)(b*SEQ + q0 + r) * EDIM + h*HDIM + dq);
        Qs[r][dq+0] = v.x * 0.125f; Qs[r][dq+1] = v.y * 0.125f;
        Qs[r][dq+2] = v.z * 0.125f; Qs[r][dq+3] = v.w * 0.125f;
    }

    float mr[4], lrow[4], o[4][4];
#pragma unroll
    for (int r = 0; r < 4; r++) {
        mr[r] = -1e30f; lrow[r] = 0.f;
#pragma unroll
        for (int c = 0; c < 4; c++) o[r][c] = 0.f;
    }

    for (int kt = 0; kt <= qt; kt++) {
        __syncthreads();
#pragma unroll
        for (int p = 0; p < 4; p++) {
            int r = p * 16 + rbase;
            size_t base = (size_t)(b*SEQ + kt*64 + r) * EDIM + h*HDIM + dq;
            float4 kv = *(const float4*)(g_qkv + base + DMODEL);
            float4 vv = *(const float4*)(g_qkv + base + 2*DMODEL);
            Ks[r][dq+0] = kv.x; Ks[r][dq+1] = kv.y; Ks[r][dq+2] = kv.z; Ks[r][dq+3] = kv.w;
            Vs[r][dq+0] = vv.x; Vs[r][dq+1] = vv.y; Vs[r][dq+2] = vv.z; Vs[r][dq+3] = vv.w;
        }
        __syncthreads();

        float sacc[4][4] = {};
#pragma unroll 8
        for (int d = 0; d < 64; d++) {
            float a[4], bb[4];
#pragma unroll
            for (int r = 0; r < 4; r++) a[r] = Qs[ty*4 + r][d];
#pragma unroll
            for (int c = 0; c < 4; c++) bb[c] = Ks[tx*4 + c][d];
#pragma unroll
            for (int r = 0; r < 4; r++)
#pragma unroll
                for (int c = 0; c < 4; c++) sacc[r][c] += a[r] * bb[c];
        }

        if (kt == qt) {
#pragma unroll
            for (int r = 0; r < 4; r++)
#pragma unroll
                for (int c = 0; c < 4; c++)
                    if (ty*4 + r < tx*4 + c) sacc[r][c] = -1e30f;
        }

#pragma unroll
        for (int r = 0; r < 4; r++) {
            float rm = fmaxf(fmaxf(sacc[r][0], sacc[r][1]), fmaxf(sacc[r][2], sacc[r][3]));
#pragma unroll
            for (int off = 8; off > 0; off >>= 1)
                rm = fmaxf(rm, __shfl_xor_sync(0xffffffffu, rm, off, 16));
            float mnew = fmaxf(mr[r], rm);
            float pr[4]; float rs = 0.f;
#pragma unroll
            for (int c = 0; c < 4; c++) { pr[c] = __expf(sacc[r][c] - mnew); rs += pr[c]; }
#pragma unroll
            for (int off = 8; off > 0; off >>= 1)
                rs += __shfl_xor_sync(0xffffffffu, rs, off, 16);
            float alpha = __expf(mr[r] - mnew);
            lrow[r] = lrow[r] * alpha + rs;
            mr[r] = mnew;
#pragma unroll
            for (int c = 0; c < 4; c++) o[r][c] *= alpha;
#pragma unroll
            for (int c = 0; c < 4; c++) Ps[ty*4 + r][tx*4 + c] = pr[c];
        }
        __syncthreads();

#pragma unroll 8
        for (int j = 0; j < 64; j++) {
            float a[4], bb[4];
#pragma unroll
            for (int r = 0; r < 4; r++) a[r] = Ps[ty*4 + r][j];
#pragma unroll
            for (int c = 0; c < 4; c++) bb[c] = Vs[j][tx*4 + c];
#pragma unroll
            for (int r = 0; r < 4; r++)
#pragma unroll
                for (int c = 0; c < 4; c++) o[r][c] += a[r] * bb[c];
        }
    }

#pragma unroll
    for (int r = 0; r < 4; r++) {
        float invl = 1.0f / lrow[r];
        int row = b*SEQ + q0 + ty*4 + r;
#pragma unroll
        for (int c = 0; c < 4; c++)
            g_attn[(size_t)row * DMODEL + h*HDIM + tx*4 + c] = o[r][c] * invl;
    }
}

// ===========================================================================
extern "C" void kernel_launch(void* const* d_in, const int* in_sizes, int n_in,
                              void* d_out, int out_size) {
    const float* x      = (const float*)d_in[0];
    const float* norm_w = (const float*)d_in[1];
    const float* w_qkv  = (const float*)d_in[2];
    const float* w_out  = (const float*)d_in[3];
    float* out = (float*)d_out;

    __nv_bfloat16 *p_abf, *p_bbf, *p_bbf2;
    float *p_qkv, *p_attn;
    cudaGetSymbolAddress((void**)&p_abf,  g_abf);
    cudaGetSymbolAddress((void**)&p_bbf,  g_bbf);
    cudaGetSymbolAddress((void**)&p_bbf2, g_bbf2);
    cudaGetSymbolAddress((void**)&p_qkv,  g_qkv);
    cudaGetSymbolAddress((void**)&p_attn, g_attn);

    // 1. RMSNorm -> A' (bf16 split)
    rmsnorm_kernel<<<MROWS, 256>>>(x, norm_w);

    // 2. w_qkv -> B'
    convert_w_kernel<<<(EDIM*DMODEL)/256, 256>>>(w_qkv, p_bbf, EDIM*DMODEL);

    // 3. QKV projection (HMMA): g_qkv[4096,3072] = A' @ B'^T
    gemm_mma_kernel<false><<<dim3(EDIM/128, MROWS/128), 256>>>(
        p_abf, p_bbf, nullptr, p_qkv, EDIM);

    // 4. RoPE (in place on q,k sections)
    rope_kernel<<<(MROWS * 2 * NHEADS * 32) / 256, 256>>>();

    // 5. Causal flash attention (fp32)
    int smem = 4 * 64 * 65 * (int)sizeof(float);
    cudaFuncSetAttribute(attn_kernel, cudaFuncAttributeMaxDynamicSharedMemorySize, smem);
    attn_kernel<<<dim3(SEQ/64, NHEADS, BATCH), 256, smem>>>();

    // 6. attn output + w_out -> bf16 split
    convert_a_kernel<<<(MROWS*DMODEL)/256, 256>>>(p_attn, p_abf, MROWS*DMODEL);
    convert_w_kernel<<<(DMODEL*DMODEL)/256, 256>>>(w_out, p_bbf2, DMODEL*DMODEL);

    // 7. Output projection + residual (HMMA): out = x + A' @ B'^T
    gemm_mma_kernel<true><<<dim3(DMODEL/128, MROWS/128), 256>>>(
        p_abf, p_bbf2, x, out, DMODEL);
}

// round 4
// speedup vs baseline: 2.2106x; 1.5064x over previous
#include <cuda_runtime.h>
#include <cuda_bf16.h>
#include <math.h>
#include <stdint.h>

#define BATCH   2
#define SEQ     2048
#define DMODEL  1024
#define NHEADS  16
#define HDIM    64
#define MROWS   (BATCH*SEQ)        // 4096
#define EDIM    (3*DMODEL)         // 3072
#define K3      (3*DMODEL)         // expanded split-K = 3072
#define NK      (K3/32)            // 96 k-chunks of 32
#define BH      (BATCH*NHEADS)     // 32

// Scratch (device globals; no runtime allocation allowed)
__device__ __align__(128) __nv_bfloat16 g_abf[MROWS*K3];     // A' (hi,lo,hi)
__device__ __align__(128) __nv_bfloat16 g_bbf[EDIM*K3];      // B' for w_qkv
__device__ __align__(128) __nv_bfloat16 g_bbf2[DMODEL*K3];   // B' for w_out
__device__ float g_qkv[MROWS*EDIM];
// head-major split q/k/v: [section(q,k,v)][part(hi,lo)][bh][t][d]
__device__ __align__(128) __nv_bfloat16 g_split[(size_t)6*BH*SEQ*HDIM];
#define SEC_ELEMS ((size_t)BH*SEQ*HDIM)

// ===========================================================================
// helpers
// ===========================================================================
__device__ __forceinline__ uint32_t smem_u32(const void* p) {
    uint32_t a;
    asm("{ .reg .u64 t; cvta.to.shared.u64 t, %1; cvt.u32.u64 %0, t; }" : "=r"(a) : "l"(p));
    return a;
}
__device__ __forceinline__ void cp16(uint32_t smem, const void* g) {
    asm volatile("cp.async.cg.shared.global [%0], [%1], 16;" :: "r"(smem), "l"(g) : "memory");
}
__device__ __forceinline__ void cp_commit() {
    asm volatile("cp.async.commit_group;" ::: "memory");
}
template<int N> __device__ __forceinline__ void cp_wait() {
    asm volatile("cp.async.wait_group %0;" :: "n"(N) : "memory");
}
__device__ __forceinline__ void ldsm4(uint32_t& r0, uint32_t& r1, uint32_t& r2, uint32_t& r3,
                                      uint32_t addr) {
    asm volatile("ldmatrix.sync.aligned.m8n8.x4.shared.b16 {%0,%1,%2,%3}, [%4];"
                 : "=r"(r0), "=r"(r1), "=r"(r2), "=r"(r3) : "r"(addr));
}
__device__ __forceinline__ void ldsm4t(uint32_t& r0, uint32_t& r1, uint32_t& r2, uint32_t& r3,
                                       uint32_t addr) {
    asm volatile("ldmatrix.sync.aligned.m8n8.x4.trans.shared.b16 {%0,%1,%2,%3}, [%4];"
                 : "=r"(r0), "=r"(r1), "=r"(r2), "=r"(r3) : "r"(addr));
}
__device__ __forceinline__ void mma16816(float* d, const uint32_t* a, const uint32_t* b) {
    asm volatile("mma.sync.aligned.m16n8k16.row.col.f32.bf16.bf16.f32 "
                 "{%0,%1,%2,%3}, {%4,%5,%6,%7}, {%8,%9}, {%0,%1,%2,%3};"
                 : "+f"(d[0]), "+f"(d[1]), "+f"(d[2]), "+f"(d[3])
                 : "r"(a[0]), "r"(a[1]), "r"(a[2]), "r"(a[3]), "r"(b[0]), "r"(b[1]));
}
__device__ __forceinline__ uint32_t pack_bf16(float a, float b) {
    __nv_bfloat162 t = __floats2bfloat162_rn(a, b);
    return *(uint32_t*)&t;
}

// ===========================================================================
// K1: RMSNorm -> bf16-split A' (hi, lo, hi).
// ===========================================================================
__global__ void rmsnorm_kernel(const float* __restrict__ x, const float* __restrict__ w) {
    int row = blockIdx.x;
    int tid = threadIdx.x;
    const float* xr = x + (size_t)row * DMODEL;
    float v[4];
    float ss = 0.f;
#pragma unroll
    for (int i = 0; i < 4; i++) { v[i] = xr[tid + i*256]; ss += v[i]*v[i]; }
    __shared__ float red[256];
    red[tid] = ss;
    __syncthreads();
#pragma unroll
    for (int off = 128; off > 0; off >>= 1) {
        if (tid < off) red[tid] += red[tid + off];
        __syncthreads();
    }
    float inv = rsqrtf(red[0] * (1.0f / DMODEL) + 1e-6f);
    __nv_bfloat16* d = g_abf + (size_t)row * K3;
#pragma unroll
    for (int i = 0; i < 4; i++) {
        int col = tid + i*256;
        float y = v[i] * inv * w[col];
        __nv_bfloat16 hi = __float2bfloat16(y);
        __nv_bfloat16 lo = __float2bfloat16(y - __bfloat162float(hi));
        d[col] = hi; d[DMODEL + col] = lo; d[2*DMODEL + col] = hi;
    }
}

// ===========================================================================
// Weight conversion: fp32 [rows,1024] -> bf16-split [rows,3072] (hi,hi,lo)
// ===========================================================================
__global__ void convert_w_kernel(const float* __restrict__ src, __nv_bfloat16* __restrict__ dst,
                                 int total) {
    int idx = blockIdx.x * 256 + threadIdx.x;
    if (idx >= total) return;
    int n = idx >> 10, k = idx & 1023;
    float x = src[idx];
    __nv_bfloat16 hi = __float2bfloat16(x);
    __nv_bfloat16 lo = __float2bfloat16(x - __bfloat162float(hi));
    __nv_bfloat16* d = dst + (size_t)n * K3;
    d[k] = hi; d[DMODEL + k] = hi; d[2*DMODEL + k] = lo;
}

// ===========================================================================
// HMMA GEMM (unchanged from round 3, passing): C = A'B'^T (+res)
// ===========================================================================
template<bool RES>
__global__ __launch_bounds__(256) void gemm_mma_kernel(
    const __nv_bfloat16* __restrict__ A, const __nv_bfloat16* __restrict__ Bw,
    const float* __restrict__ Rsd, float* __restrict__ C, int N)
{
    __shared__ __align__(128) __nv_bfloat16 sA[2][128*40];
    __shared__ __align__(128) __nv_bfloat16 sB[2][128*40];

    int tid = threadIdx.x, lid = tid & 31, wid = tid >> 5;
    int wm = (wid & 1) * 64;
    int wn = (wid >> 1) * 32;
    int m0 = blockIdx.y * 128, n0 = blockIdx.x * 128;

    int ldrow = tid >> 1;
    int ldcol = (tid & 1) * 32;
    const char* gA = (const char*)(A  + (size_t)(m0 + ldrow) * K3) + ldcol;
    const char* gB = (const char*)(Bw + (size_t)(n0 + ldrow) * K3) + ldcol;

    auto prefetch = [&](int c) {
        int s = c & 1;
        uint32_t da = smem_u32(&sA[s][ldrow * 40]) + (uint32_t)ldcol;
        uint32_t db = smem_u32(&sB[s][ldrow * 40]) + (uint32_t)ldcol;
        const char* a = gA + (size_t)c * 64;
        const char* b = gB + (size_t)c * 64;
        cp16(da, a);      cp16(da + 16, a + 16);
        cp16(db, b);      cp16(db + 16, b + 16);
        cp_commit();
    };

    float acc[4][4][4] = {};

    prefetch(0); prefetch(1);

    int g  = lid >> 3, r8 = lid & 7;
    int a_m = wm + (g & 1) * 8 + r8;
    int a_k = (g >> 1) * 8;
    int b_n = wn + (g >> 1) * 8 + r8;
    int b_k = (g & 1) * 8;

    for (int kt = 0; kt < NK; kt++) {
        int s = kt & 1;
        if (kt + 1 < NK) cp_wait<1>(); else cp_wait<0>();
        __syncthreads();

        uint32_t baseA = smem_u32(&sA[s][0]);
        uint32_t baseB = smem_u32(&sB[s][0]);
#pragma unroll
        for (int ks = 0; ks < 2; ks++) {
            uint32_t a[4][4], b[4][2];
#pragma unroll
            for (int mt = 0; mt < 4; mt++) {
                uint32_t addr = baseA + (uint32_t)(a_m + mt*16) * 80u
                                      + (uint32_t)(a_k + ks*16) * 2u;
                ldsm4(a[mt][0], a[mt][1], a[mt][2], a[mt][3], addr);
            }
#pragma unroll
            for (int nt = 0; nt < 2; nt++) {
                uint32_t r0, r1, r2, r3;
                uint32_t addr = baseB + (uint32_t)(b_n + nt*16) * 80u
                                      + (uint32_t)(b_k + ks*16) * 2u;
                ldsm4(r0, r1, r2, r3, addr);
                b[nt*2][0] = r0;   b[nt*2][1] = r1;
                b[nt*2+1][0] = r2; b[nt*2+1][1] = r3;
            }
#pragma unroll
            for (int mt = 0; mt < 4; mt++)
#pragma unroll
                for (int nn = 0; nn < 4; nn++)
                    mma16816(acc[mt][nn], a[mt], b[nn]);
        }
        __syncthreads();
        if (kt + 2 < NK) prefetch(kt + 2);
    }

    int row = lid >> 2, col = (lid & 3) * 2;
#pragma unroll
    for (int mt = 0; mt < 4; mt++) {
#pragma unroll
        for (int nn = 0; nn < 4; nn++) {
            int m = m0 + wm + mt*16 + row;
            int n = n0 + wn + nn*8 + col;
            float2 v0 = make_float2(acc[mt][nn][0], acc[mt][nn][1]);
            float2 v1 = make_float2(acc[mt][nn][2], acc[mt][nn][3]);
            if (RES) {
                float2 q0 = *(const float2*)(Rsd + (size_t)m * N + n);
                float2 q1 = *(const float2*)(Rsd + (size_t)(m+8) * N + n);
                v0.x += q0.x; v0.y += q0.y;
                v1.x += q1.x; v1.y += q1.y;
            }
            *(float2*)(C + (size_t)m * N + n)     = v0;
            *(float2*)(C + (size_t)(m+8) * N + n) = v1;
        }
    }
}

// ===========================================================================
// K3: RoPE + fp32->bf16 hi/lo split into head-major arrays.
// Q scaled by 1/sqrt(HDIM). One thread per (m, section, head, dpair).
// ===========================================================================
__global__ void rope_split_kernel() {
    int idx = blockIdx.x * 256 + threadIdx.x;   // MROWS*3*16*32 total
    int d = idx & 31;
    int h = (idx >> 5) & 15;
    int ms = idx >> 9;            // m*3 + s
    int s = ms % 3;
    int m = ms / 3;
    int t = m & (SEQ - 1);
    int b = m >> 11;
    const float* src = g_qkv + (size_t)m * EDIM + s * DMODEL + h * HDIM;
    float f1 = src[d], f2 = src[d + 32];
    float y1, y2;
    if (s < 2) {
        float inv_freq = powf(10000.0f, -(float)d * (1.0f / 32.0f));
        float ang = (float)t * inv_freq;
        float sn, cs;
        sincosf(ang, &sn, &cs);
        y1 = f1 * cs - f2 * sn;
        y2 = f2 * cs + f1 * sn;
        if (s == 0) { y1 *= 0.125f; y2 *= 0.125f; }
    } else { y1 = f1; y2 = f2; }
    size_t base = (size_t)(s * 2) * SEC_ELEMS + ((size_t)(b * NHEADS + h) * SEQ + t) * HDIM;
    __nv_bfloat16 h1 = __float2bfloat16(y1);
    __nv_bfloat16 h2 = __float2bfloat16(y2);
    g_split[base + d]      = h1;
    g_split[base + d + 32] = h2;
    size_t lb = base + SEC_ELEMS;
    g_split[lb + d]      = __float2bfloat16(y1 - __bfloat162float(h1));
    g_split[lb + d + 32] = __float2bfloat16(y2 - __bfloat162float(h2));
}

// ===========================================================================
// K4: HMMA causal flash attention, split-bf16 operands, fp32 softmax.
// grid (SEQ/64, NHEADS, BATCH), 128 threads (4 warps x 16 q-rows).
// Output written directly in split-A' layout into g_abf.
// ===========================================================================
#define ATS 72                         // smem row stride in halfs
#define AT_TILE (64*ATS)               // one 64x64 array
#define ATT_SMEM ((2 + 8) * AT_TILE * 2)   // bytes = 92160

__global__ __launch_bounds__(128) void attn_mma_kernel() {
    extern __shared__ __nv_bfloat16 sh[];
    __nv_bfloat16* Qh = sh;
    __nv_bfloat16* Ql = sh + AT_TILE;
    __nv_bfloat16* KV = sh + 2 * AT_TILE;   // stage s: +s*4*AT_TILE; [Khi,Klo,Vhi,Vlo]

    int qt = blockIdx.x, hh = blockIdx.y, b = blockIdx.z;
    int bh = b * NHEADS + hh;
    int tid = threadIdx.x;
    int lid = tid & 31, wid = tid >> 5;
    int q0 = qt * 64;

    const __nv_bfloat16* gqh = g_split + 0*SEC_ELEMS + (size_t)bh * SEQ * HDIM;
    const __nv_bfloat16* gql = g_split + 1*SEC_ELEMS + (size_t)bh * SEQ * HDIM;
    const __nv_bfloat16* gkh = g_split + 2*SEC_ELEMS + (size_t)bh * SEQ * HDIM;
    const __nv_bfloat16* gkl = g_split + 3*SEC_ELEMS + (size_t)bh * SEQ * HDIM;
    const __nv_bfloat16* gvh = g_split + 4*SEC_ELEMS + (size_t)bh * SEQ * HDIM;
    const __nv_bfloat16* gvl = g_split + 5*SEC_ELEMS + (size_t)bh * SEQ * HDIM;

    int ldrow = tid >> 1;          // 0..63
    int ldh   = (tid & 1) * 32;    // halfs offset within row

    // Q load (part of group 0)
    {
        const __nv_bfloat16* s0 = gqh + (size_t)(q0 + ldrow) * HDIM + ldh;
        const __nv_bfloat16* s1 = gql + (size_t)(q0 + ldrow) * HDIM + ldh;
        uint32_t d0 = smem_u32(Qh + ldrow * ATS + ldh);
        uint32_t d1 = smem_u32(Ql + ldrow * ATS + ldh);
#pragma unroll
        for (int i = 0; i < 4; i++) {
            cp16(d0 + i*16, s0 + i*8);
            cp16(d1 + i*16, s1 + i*8);
        }
    }

    auto prefetch = [&](int kt) {
        int s = kt & 1;
        __nv_bfloat16* base = KV + s * 4 * AT_TILE;
        size_t gr = (size_t)(kt * 64 + ldrow) * HDIM + ldh;
        const __nv_bfloat16* srcs[4] = { gkh + gr, gkl + gr, gvh + gr, gvl + gr };
#pragma unroll
        for (int a = 0; a < 4; a++) {
            uint32_t dst = smem_u32(base + a * AT_TILE + ldrow * ATS + ldh);
#pragma unroll
            for (int i = 0; i < 4; i++) cp16(dst + i*16, srcs[a] + i*8);
        }
        cp_commit();
    };
    prefetch(0);   // group 0 = Q + tile 0

    // state
    float m0 = -1e30f, m1 = -1e30f, l0 = 0.f, l1 = 0.f;
    float oacc[8][4] = {};

    int g  = lid >> 3, r8 = lid & 7;
    int a_row = wid * 16 + (g & 1) * 8 + r8;   // Q smem row
    int a_kof = (g >> 1) * 8;                  // + kc*16
    int b_row = (g >> 1) * 8 + r8;             // K smem row within 16-pair (+p*16)
    int b_kof = (g & 1) * 8;
    int v_row = lid & 15;                      // + kc*16
    int v_col = (lid >> 4) * 8;                // + p*16
    int qrow_loc = wid * 16 + (lid >> 2);      // local q row for c0/c1

    for (int kt = 0; kt <= qt; kt++) {
        __syncthreads();
        if (kt < qt) { prefetch(kt + 1); cp_wait<1>(); } else { cp_wait<0>(); }
        __syncthreads();

        const __nv_bfloat16* Kh = KV + (kt & 1) * 4 * AT_TILE;
        const __nv_bfloat16* Kl = Kh + AT_TILE;
        const __nv_bfloat16* Vh = Kl + AT_TILE;
        const __nv_bfloat16* Vl = Vh + AT_TILE;
        uint32_t bKh = smem_u32(Kh), bKl = smem_u32(Kl);
        uint32_t bVh = smem_u32(Vh), bVl = smem_u32(Vl);
        uint32_t bQh = smem_u32(Qh), bQl = smem_u32(Ql);

        // ---- S = Q K^T (split-3) ----
        float sacc[8][4] = {};
#pragma unroll
        for (int kc = 0; kc < 4; kc++) {
            uint32_t ah[4], al[4];
            uint32_t aoff = (uint32_t)(a_row * ATS + kc*16 + a_kof) * 2u;
            ldsm4(ah[0], ah[1], ah[2], ah[3], bQh + aoff);
            ldsm4(al[0], al[1], al[2], al[3], bQl + aoff);
            uint32_t bhf[8][2], blf[8][2];
#pragma unroll
            for (int p = 0; p < 4; p++) {
                uint32_t boff = (uint32_t)((p*16 + b_row) * ATS + kc*16 + b_kof) * 2u;
                uint32_t r0, r1, r2, r3;
                ldsm4(r0, r1, r2, r3, bKh + boff);
                bhf[2*p][0] = r0; bhf[2*p][1] = r1;
                bhf[2*p+1][0] = r2; bhf[2*p+1][1] = r3;
                ldsm4(r0, r1, r2, r3, bKl + boff);
                blf[2*p][0] = r0; blf[2*p][1] = r1;
                blf[2*p+1][0] = r2; blf[2*p+1][1] = r3;
            }
#pragma unroll
            for (int j = 0; j < 8; j++) {
                mma16816(sacc[j], ah, bhf[j]);
                mma16816(sacc[j], al, bhf[j]);
                mma16816(sacc[j], ah, blf[j]);
            }
        }

        // ---- causal mask on diagonal tile ----
        if (kt == qt) {
#pragma unroll
            for (int j = 0; j < 8; j++) {
                int col = j*8 + (lid & 3) * 2;
                if (col     > qrow_loc)     sacc[j][0] = -1e30f;
                if (col + 1 > qrow_loc)     sacc[j][1] = -1e30f;
                if (col     > qrow_loc + 8) sacc[j][2] = -1e30f;
                if (col + 1 > qrow_loc + 8) sacc[j][3] = -1e30f;
            }
        }

        // ---- online softmax (rows qrow_loc and +8) ----
        float mx0 = -1e30f, mx1 = -1e30f;
#pragma unroll
        for (int j = 0; j < 8; j++) {
            mx0 = fmaxf(mx0, fmaxf(sacc[j][0], sacc[j][1]));
            mx1 = fmaxf(mx1, fmaxf(sacc[j][2], sacc[j][3]));
        }
        mx0 = fmaxf(mx0, __shfl_xor_sync(0xffffffffu, mx0, 1));
        mx0 = fmaxf(mx0, __shfl_xor_sync(0xffffffffu, mx0, 2));
        mx1 = fmaxf(mx1, __shfl_xor_sync(0xffffffffu, mx1, 1));
        mx1 = fmaxf(mx1, __shfl_xor_sync(0xffffffffu, mx1, 2));
        float mn0 = fmaxf(m0, mx0), mn1 = fmaxf(m1, mx1);
        float al0 = __expf(m0 - mn0), al1 = __expf(m1 - mn1);
        float s0 = 0.f, s1 = 0.f;
#pragma unroll
        for (int j = 0; j < 8; j++) {
            sacc[j][0] = __expf(sacc[j][0] - mn0);
            sacc[j][1] = __expf(sacc[j][1] - mn0);
            sacc[j][2] = __expf(sacc[j][2] - mn1);
            sacc[j][3] = __expf(sacc[j][3] - mn1);
            s0 += sacc[j][0] + sacc[j][1];
            s1 += sacc[j][2] + sacc[j][3];
        }
        s0 += __shfl_xor_sync(0xffffffffu, s0, 1);
        s0 += __shfl_xor_sync(0xffffffffu, s0, 2);
        s1 += __shfl_xor_sync(0xffffffffu, s1, 1);
        s1 += __shfl_xor_sync(0xffffffffu, s1, 2);
        l0 = l0 * al0 + s0;  l1 = l1 * al1 + s1;
        m0 = mn0;  m1 = mn1;
#pragma unroll
        for (int j = 0; j < 8; j++) {
            oacc[j][0] *= al0; oacc[j][1] *= al0;
            oacc[j][2] *= al1; oacc[j][3] *= al1;
        }

        // ---- build split P fragments (C-frag -> A-frag identity) ----
        uint32_t ph01[8], ph23[8], pl01[8], pl23[8];
#pragma unroll
        for (int j = 0; j < 8; j++) {
            float p0 = sacc[j][0], p1 = sacc[j][1], p2 = sacc[j][2], p3 = sacc[j][3];
            __nv_bfloat16 h0 = __float2bfloat16(p0), h1 = __float2bfloat16(p1);
            __nv_bfloat16 h2 = __float2bfloat16(p2), h3 = __float2bfloat16(p3);
            ph01[j] = ((uint32_t)*(uint16_t*)&h1 << 16) | *(uint16_t*)&h0;
            ph23[j] = ((uint32_t)*(uint16_t*)&h3 << 16) | *(uint16_t*)&h2;
            pl01[j] = pack_bf16(p0 - __bfloat162float(h0), p1 - __bfloat162float(h1));
            pl23[j] = pack_bf16(p2 - __bfloat162float(h2), p3 - __bfloat162float(h3));
        }

        // ---- O += P V (split-3), V via ldmatrix.trans ----
#pragma unroll
        for (int kc = 0; kc < 4; kc++) {
            uint32_t aH[4] = { ph01[2*kc], ph23[2*kc], ph01[2*kc+1], ph23[2*kc+1] };
            uint32_t aL[4] = { pl01[2*kc], pl23[2*kc], pl01[2*kc+1], pl23[2*kc+1] };
#pragma unroll
            for (int p = 0; p < 4; p++) {
                uint32_t voff = (uint32_t)((kc*16 + v_row) * ATS + p*16 + v_col) * 2u;
                uint32_t h0, h1, h2, h3, l0r, l1r, l2r, l3r;
                ldsm4t(h0, h1, h2, h3, bVh + voff);
                ldsm4t(l0r, l1r, l2r, l3r, bVl + voff);
                uint32_t bv0[2] = { h0, h1 }, bv1[2] = { h2, h3 };
                uint32_t bw0[2] = { l0r, l1r }, bw1[2] = { l2r, l3r };
                mma16816(oacc[2*p],   aH, bv0);
                mma16816(oacc[2*p],   aL, bv0);
                mma16816(oacc[2*p],   aH, bw0);
                mma16816(oacc[2*p+1], aH, bv1);
                mma16816(oacc[2*p+1], aL, bv1);
                mma16816(oacc[2*p+1], aH, bw1);
            }
        }
    }

    // ---- epilogue: normalize, write split-A' directly into g_abf ----
    float inv0 = 1.0f / l0, inv1 = 1.0f / l1;
    int mg0 = b * SEQ + q0 + qrow_loc;
    int mg1 = mg0 + 8;
#pragma unroll
    for (int j = 0; j < 8; j++) {
        int col = hh * HDIM + j*8 + (lid & 3) * 2;
        float v0 = oacc[j][0] * inv0, v1 = oacc[j][1] * inv0;
        float v2 = oacc[j][2] * inv1, v3 = oacc[j][3] * inv1;
        __nv_bfloat16 h0 = __float2bfloat16(v0), h1 = __float2bfloat16(v1);
        __nv_bfloat16 h2 = __float2bfloat16(v2), h3 = __float2bfloat16(v3);
        __nv_bfloat162 hp0; hp0.x = h0; hp0.y = h1;
        __nv_bfloat162 hp1; hp1.x = h2; hp1.y = h3;
        __nv_bfloat162 lp0; lp0.x = __float2bfloat16(v0 - __bfloat162float(h0));
                            lp0.y = __float2bfloat16(v1 - __bfloat162float(h1));
        __nv_bfloat162 lp1; lp1.x = __float2bfloat16(v2 - __bfloat162float(h2));
                            lp1.y = __float2bfloat16(v3 - __bfloat162float(h3));
        __nv_bfloat16* r0p = g_abf + (size_t)mg0 * K3 + col;
        __nv_bfloat16* r1p = g_abf + (size_t)mg1 * K3 + col;
        *(__nv_bfloat162*)(r0p)              = hp0;
        *(__nv_bfloat162*)(r0p + DMODEL)     = lp0;
        *(__nv_bfloat162*)(r0p + 2*DMODEL)   = hp0;
        *(__nv_bfloat162*)(r1p)              = hp1;
        *(__nv_bfloat162*)(r1p + DMODEL)     = lp1;
        *(__nv_bfloat162*)(r1p + 2*DMODEL)   = hp1;
    }
}

// ===========================================================================
extern "C" void kernel_launch(void* const* d_in, const int* in_sizes, int n_in,
                              void* d_out, int out_size) {
    const float* x      = (const float*)d_in[0];
    const float* norm_w = (const float*)d_in[1];
    const float* w_qkv  = (const float*)d_in[2];
    const float* w_out  = (const float*)d_in[3];
    float* out = (float*)d_out;

    __nv_bfloat16 *p_abf, *p_bbf, *p_bbf2;
    float *p_qkv;
    cudaGetSymbolAddress((void**)&p_abf,  g_abf);
    cudaGetSymbolAddress((void**)&p_bbf,  g_bbf);
    cudaGetSymbolAddress((void**)&p_bbf2, g_bbf2);
    cudaGetSymbolAddress((void**)&p_qkv,  g_qkv);

    cudaFuncSetAttribute(attn_mma_kernel,
                         cudaFuncAttributeMaxDynamicSharedMemorySize, ATT_SMEM);

    // 1. RMSNorm -> A'
    rmsnorm_kernel<<<MROWS, 256>>>(x, norm_w);

    // 2. w_qkv -> B'
    convert_w_kernel<<<(EDIM*DMODEL)/256, 256>>>(w_qkv, p_bbf, EDIM*DMODEL);

    // 3. QKV projection (HMMA)
    gemm_mma_kernel<false><<<dim3(EDIM/128, MROWS/128), 256>>>(
        p_abf, p_bbf, nullptr, p_qkv, EDIM);

    // 4. RoPE + split into head-major bf16 hi/lo
    rope_split_kernel<<<(MROWS * 3 * NHEADS * 32) / 256, 256>>>();

    // 5. HMMA causal flash attention (writes split-A' into g_abf)
    attn_mma_kernel<<<dim3(SEQ/64, NHEADS, BATCH), 128, ATT_SMEM>>>();

    // 6. w_out -> B'
    convert_w_kernel<<<(DMODEL*DMODEL)/256, 256>>>(w_out, p_bbf2, DMODEL*DMODEL);

    // 7. Output projection + residual (HMMA)
    gemm_mma_kernel<true><<<dim3(DMODEL/128, MROWS/128), 256>>>(
        p_abf, p_bbf2, x, out, DMODEL);
}